// round 13
// baseline (speedup 1.0000x reference)
#include <cuda_runtime.h>
#include <cuda_fp16.h>
#include <cstdint>

#define BATCH 16
#define HW    16384
#define C     64
#define CHUNKS 32            // 512 rows per CTA

__device__ float g_partial[BATCH * CHUNKS * C * C];   // 8 MB scratch
__device__ float g_attn[BATCH * C * C];
__device__ int   g_cnt[BATCH];                        // zero-init, self-resetting

// ---------------------------------------------------------------------------
// helpers
// ---------------------------------------------------------------------------
__device__ __forceinline__ uint32_t smem_u32(const void* p) {
    uint32_t a;
    asm("{ .reg .u64 t; cvta.to.shared.u64 t, %1; cvt.u32.u64 %0, t; }"
        : "=r"(a) : "l"(p));
    return a;
}
__device__ __forceinline__ uint32_t sw128(uint32_t o) {
    return o ^ ((o >> 3) & 0x70);
}
__device__ __forceinline__ uint32_t h2u(__half2 h) {
    return *reinterpret_cast<uint32_t*>(&h);
}

#define LDSM4T(r, a)                                                          \
    asm volatile("ldmatrix.sync.aligned.m8n8.x4.trans.shared.b16 "            \
                 "{%0,%1,%2,%3}, [%4];"                                       \
                 : "=r"((r)[0]), "=r"((r)[1]), "=r"((r)[2]), "=r"((r)[3])     \
                 : "r"(a))
#define LDSM4(r, a)                                                           \
    asm volatile("ldmatrix.sync.aligned.m8n8.x4.shared.b16 "                  \
                 "{%0,%1,%2,%3}, [%4];"                                       \
                 : "=r"((r)[0]), "=r"((r)[1]), "=r"((r)[2]), "=r"((r)[3])     \
                 : "r"(a))
#define MMA(d, a, b0, b1)                                                     \
    asm volatile("mma.sync.aligned.m16n8k16.row.col.f32.f16.f16.f32 "         \
                 "{%0,%1,%2,%3}, {%4,%5,%6,%7}, {%8,%9}, {%0,%1,%2,%3};"      \
                 : "+f"((d)[0]), "+f"((d)[1]), "+f"((d)[2]), "+f"((d)[3])     \
                 : "r"((a)[0]), "r"((a)[1]), "r"((a)[2]), "r"((a)[3]),        \
                   "r"(b0), "r"(b1))

// tile: 64 rows x 64 fp16 cols, 128B row stride, SW128 swizzle, 8KB
#define TILE 8192

// exact Dekker split of 4 floats into hi/lo fp16x2 pairs
__device__ __forceinline__ void split4(float4 x, uint32_t& h0, uint32_t& h1,
                                       uint32_t& l0, uint32_t& l1) {
    __half2 a01 = __floats2half2_rn(x.x, x.y);
    __half2 a23 = __floats2half2_rn(x.z, x.w);
    float2 f01 = __half22float2(a01);
    float2 f23 = __half22float2(a23);
    __half2 b01 = __floats2half2_rn(x.x - f01.x, x.y - f01.y);
    __half2 b23 = __floats2half2_rn(x.z - f23.x, x.w - f23.y);
    h0 = h2u(a01); h1 = h2u(a23); l0 = h2u(b01); l1 = h2u(b23);
}

// ---------------------------------------------------------------------------
// Kernel 1: partial scores + FUSED last-CTA softmax.
// 8 warps, 32x32 subtiles, 2-way k-split, double-buffered tiles.
// After writing its slice, the last CTA of each batch reduces 32 L2-resident
// slices and computes softmax -> g_attn. No k2 launch.
// ---------------------------------------------------------------------------
__global__ void __launch_bounds__(256, 2)
k1_scores(const float* __restrict__ Q, const float* __restrict__ K) {
    __shared__ __align__(1024) uint8_t sm[8 * TILE];   // [buf][Qh Ql Kh Kl]
    __shared__ int isLast;
    uint32_t sb = smem_u32(sm);

    int t = threadIdx.x, lane = t & 31, w = t >> 5;
    int b = blockIdx.x >> 5;
    int chunk = blockIdx.x & 31;
    int wk = w >> 2;
    int sub = w & 3;
    int qb32 = (sub >> 1) * 32;
    int nb32 = (sub & 1) * 32;

    const float* Qb = Q + ((size_t)b * HW + chunk * 512) * C;
    const float* Kb = K + ((size_t)b * HW + chunk * 512) * C;

    int rr[4], cc[4];
#pragma unroll
    for (int it = 0; it < 4; ++it) {
        int idx = t + it * 256;
        rr[it] = idx >> 4;
        cc[it] = (idx & 15) * 4;
    }

    float d[2][4][4];
#pragma unroll
    for (int i = 0; i < 2; ++i)
#pragma unroll
        for (int j = 0; j < 4; ++j)
#pragma unroll
            for (int e = 0; e < 4; ++e) d[i][j][e] = 0.f;

    const int li = lane & 7, mi = lane >> 3;
    const int rA = ((mi & 2) << 2) + li;
    const int cA0 = qb32 + ((mi & 1) << 3);
    const int rB = ((mi & 1) << 3) + li;
    const int cBo = (mi & 2) << 2;

    float4 pq[4], pk[4];
#pragma unroll
    for (int it = 0; it < 4; ++it) {
        pq[it] = *(const float4*)(Qb + (size_t)rr[it] * C + cc[it]);
        pk[it] = *(const float4*)(Kb + (size_t)rr[it] * C + cc[it]);
    }

    for (int s = 0; s < 8; ++s) {
        uint32_t base = (uint32_t)((s & 1) * 4 * TILE);
#pragma unroll
        for (int it = 0; it < 4; ++it) {
            uint32_t off = base + sw128((uint32_t)(rr[it] * 128 + cc[it] * 2));
            uint32_t h0, h1, l0, l1;
            split4(pq[it], h0, h1, l0, l1);
            *(uint2*)(sm + 0 * TILE + off) = make_uint2(h0, h1);
            *(uint2*)(sm + 1 * TILE + off) = make_uint2(l0, l1);
            split4(pk[it], h0, h1, l0, l1);
            *(uint2*)(sm + 2 * TILE + off) = make_uint2(h0, h1);
            *(uint2*)(sm + 3 * TILE + off) = make_uint2(l0, l1);
        }
        __syncthreads();

        if (s < 7) {
            const float* Qn = Qb + (size_t)(s + 1) * 64 * C;
            const float* Kn = Kb + (size_t)(s + 1) * 64 * C;
#pragma unroll
            for (int it = 0; it < 4; ++it) {
                pq[it] = *(const float4*)(Qn + (size_t)rr[it] * C + cc[it]);
                pk[it] = *(const float4*)(Kn + (size_t)rr[it] * C + cc[it]);
            }
        }

#pragma unroll
        for (int k2i = 0; k2i < 2; ++k2i) {
            int r0 = (wk * 2 + k2i) * 16;
            uint32_t Ah[2][4], Al[2][4], Bh[2][4], Bl[2][4];
#pragma unroll
            for (int mb = 0; mb < 2; ++mb) {
                uint32_t aoff =
                    base + sw128((uint32_t)((r0 + rA) * 128 + (cA0 + mb * 16) * 2));
                LDSM4T(Ah[mb], sb + 0 * TILE + aoff);
                LDSM4T(Al[mb], sb + 1 * TILE + aoff);
            }
#pragma unroll
            for (int np = 0; np < 2; ++np) {
                uint32_t boff =
                    base + sw128((uint32_t)((r0 + rB) * 128 + (nb32 + np * 16 + cBo) * 2));
                LDSM4T(Bh[np], sb + 2 * TILE + boff);
                LDSM4T(Bl[np], sb + 3 * TILE + boff);
            }
#pragma unroll
            for (int mb = 0; mb < 2; ++mb)
#pragma unroll
                for (int np = 0; np < 2; ++np) {
                    float* d0 = d[mb][np * 2];
                    float* d1 = d[mb][np * 2 + 1];
                    MMA(d0, Ah[mb], Bh[np][0], Bh[np][1]);
                    MMA(d1, Ah[mb], Bh[np][2], Bh[np][3]);
                    MMA(d0, Ah[mb], Bl[np][0], Bl[np][1]);
                    MMA(d1, Ah[mb], Bl[np][2], Bl[np][3]);
                    MMA(d0, Al[mb], Bh[np][0], Bh[np][1]);
                    MMA(d1, Al[mb], Bh[np][2], Bh[np][3]);
                }
        }
    }

    // ---------------- epilogue: k-half reduction in smem, one slice --------
    __syncthreads();
    float* sred = (float*)sm;                      // reuse tile area
    if (wk == 1) {
#pragma unroll
        for (int mb = 0; mb < 2; ++mb)
#pragma unroll
            for (int j = 0; j < 4; ++j)
#pragma unroll
                for (int e = 0; e < 4; ++e)
                    sred[sub * 1024 + ((mb * 4 + j) * 4 + e) * 32 + lane] =
                        d[mb][j][e];
    }
    __syncthreads();
    if (wk == 0) {
#pragma unroll
        for (int mb = 0; mb < 2; ++mb)
#pragma unroll
            for (int j = 0; j < 4; ++j)
#pragma unroll
                for (int e = 0; e < 4; ++e)
                    d[mb][j][e] +=
                        sred[sub * 1024 + ((mb * 4 + j) * 4 + e) * 32 + lane];

        float* pb = g_partial + ((size_t)b * CHUNKS + chunk) * (C * C);
        int mrow0 = qb32 + (lane >> 2);
        int mcol = 2 * (lane & 3);
#pragma unroll
        for (int mb = 0; mb < 2; ++mb) {
            int r_lo = mrow0 + mb * 16;
#pragma unroll
            for (int np = 0; np < 2; ++np) {
                int c0 = nb32 + np * 16 + mcol;
                *(float2*)(pb + r_lo * C + c0) =
                    make_float2(d[mb][np * 2][0], d[mb][np * 2][1]);
                *(float2*)(pb + (r_lo + 8) * C + c0) =
                    make_float2(d[mb][np * 2][2], d[mb][np * 2][3]);
                *(float2*)(pb + r_lo * C + c0 + 8) =
                    make_float2(d[mb][np * 2 + 1][0], d[mb][np * 2 + 1][1]);
                *(float2*)(pb + (r_lo + 8) * C + c0 + 8) =
                    make_float2(d[mb][np * 2 + 1][2], d[mb][np * 2 + 1][3]);
            }
        }
    }

    // ---------------- fused last-CTA reduction + softmax -------------------
    __threadfence();
    __syncthreads();
    if (t == 0) {
        int old = atomicAdd(&g_cnt[b], 1);
        isLast = (old == CHUNKS - 1);
    }
    __syncthreads();
    if (!isLast) return;

    // reduce 32 slices (L2-resident) -> S[4096] in smem
    float* S = (float*)sm;
    const float* p0 = g_partial + (size_t)b * CHUNKS * (C * C);
    {
        float4 acc[4];
#pragma unroll
        for (int i = 0; i < 4; ++i) acc[i] = make_float4(0.f, 0.f, 0.f, 0.f);
#pragma unroll 4
        for (int ch = 0; ch < CHUNKS; ++ch) {
#pragma unroll
            for (int i = 0; i < 4; ++i) {
                float4 v = *(const float4*)(p0 + (size_t)ch * 4096 +
                                            (t + i * 256) * 4);
                acc[i].x += v.x; acc[i].y += v.y;
                acc[i].z += v.z; acc[i].w += v.w;
            }
        }
#pragma unroll
        for (int i = 0; i < 4; ++i)
            *(float4*)(S + (t + i * 256) * 4) = acc[i];
    }
    __syncthreads();

    // softmax over k for 64 rows; 8 warps x 8 rows
    float* ga = g_attn + (size_t)b * (C * C);
#pragma unroll
    for (int r = 0; r < 8; ++r) {
        int row = w * 8 + r;
        float e0 = S[row * 64 + lane];
        float e1 = S[row * 64 + 32 + lane];
        float m = fmaxf(e0, e1);
#pragma unroll
        for (int o = 16; o > 0; o >>= 1) m = fmaxf(m, __shfl_xor_sync(~0u, m, o));
        float x0 = expf(e0 - m), x1 = expf(e1 - m);
        float ssum = x0 + x1;
#pragma unroll
        for (int o = 16; o > 0; o >>= 1) ssum += __shfl_xor_sync(~0u, ssum, o);
        float inv = 1.f / ssum;
        ga[row * 64 + lane] = x0 * inv;
        ga[row * 64 + 32 + lane] = x1 * inv;
    }
    __threadfence();
    if (t == 0) g_cnt[b] = 0;     // reset for next graph replay
}

// ---------------------------------------------------------------------------
// Kernel 3 (R9 form): out[b][r][q] = sum_k attn[b][q][k] * V[b][r][k]
// A = V (non-trans, double-buffered 64-row stages). B = attn stage-constant:
// Bh fragments hoisted to registers; Bl from smem.
// ---------------------------------------------------------------------------
__global__ void __launch_bounds__(256, 2)
k3_out(const float* __restrict__ V, float* __restrict__ O) {
    __shared__ __align__(1024) uint8_t sm[6 * TILE];   // Vh0 Vl0 Vh1 Vl1 Bh Bl
    uint32_t sb = smem_u32(sm);

    int t = threadIdx.x, lane = t & 31, w = t >> 5;
    int b = blockIdx.x >> 5;
    int rg = blockIdx.x & 31;
    size_t row0 = (size_t)b * HW + rg * 512;
    int rowg = (w & 3) * 16;
    int nbase = (w >> 2) * 2;

    int rr[4], cc[4];
#pragma unroll
    for (int it = 0; it < 4; ++it) {
        int idx = t + it * 256;
        rr[it] = idx >> 4;
        cc[it] = (idx & 15) * 4;
    }

    // stage attn once: B tile [q][k] hi/lo fp16
    const float* ab = g_attn + (size_t)b * (C * C);
#pragma unroll
    for (int it = 0; it < 4; ++it) {
        uint32_t off = sw128((uint32_t)(rr[it] * 128 + cc[it] * 2));
        uint32_t h0, h1, l0, l1;
        split4(*(const float4*)(ab + rr[it] * 64 + cc[it]), h0, h1, l0, l1);
        *(uint2*)(sm + 4 * TILE + off) = make_uint2(h0, h1);
        *(uint2*)(sm + 5 * TILE + off) = make_uint2(l0, l1);
    }
    __syncthreads();   // B tiles visible for the hoisted fragment loads

    const int li = lane & 7, mi = lane >> 3;
    const int rVA = rowg + ((mi & 1) << 3) + li;
    const int cVAo = (mi & 2) << 2;
    const int rBq = ((mi & 1) << 3) + li;
    const int cBo = (mi & 2) << 2;
    int mrow = rowg + (lane >> 2);
    int mcol = 2 * (lane & 3);

    // hoist stage-constant Bh fragments: [kst][np] -> 32 regs
    uint32_t BhR[4][2][4];
#pragma unroll
    for (int kst = 0; kst < 4; ++kst)
#pragma unroll
        for (int j = 0; j < 2; ++j) {
            uint32_t boff = sw128(
                (uint32_t)(((nbase + j) * 16 + rBq) * 128 + (kst * 16 + cBo) * 2));
            LDSM4(BhR[kst][j], sb + 4 * TILE + boff);
        }

    float4 pv[4];
#pragma unroll
    for (int it = 0; it < 4; ++it)
        pv[it] = *(const float4*)(V + (row0 + rr[it]) * C + cc[it]);

    for (int s = 0; s < 8; ++s) {
        uint32_t base = (uint32_t)((s & 1) * 2 * TILE);
#pragma unroll
        for (int it = 0; it < 4; ++it) {
            uint32_t off = base + sw128((uint32_t)(rr[it] * 128 + cc[it] * 2));
            uint32_t h0, h1, l0, l1;
            split4(pv[it], h0, h1, l0, l1);
            *(uint2*)(sm + 0 * TILE + off) = make_uint2(h0, h1);
            *(uint2*)(sm + 1 * TILE + off) = make_uint2(l0, l1);
        }
        __syncthreads();   // V buf ready

        if (s < 7) {
            const float* Vn = V + (row0 + (size_t)(s + 1) * 64) * C;
#pragma unroll
            for (int it = 0; it < 4; ++it)
                pv[it] = *(const float4*)(Vn + (size_t)rr[it] * C + cc[it]);
        }

        float d[4][4];
#pragma unroll
        for (int i = 0; i < 4; ++i)
#pragma unroll
            for (int j = 0; j < 4; ++j) d[i][j] = 0.f;

#pragma unroll
        for (int kst = 0; kst < 4; ++kst) {
            int k0 = kst * 16;
            uint32_t Ah[4], Al[4];
            uint32_t aoff = base + sw128((uint32_t)(rVA * 128 + (k0 + cVAo) * 2));
            LDSM4(Ah, sb + 0 * TILE + aoff);
            LDSM4(Al, sb + 1 * TILE + aoff);
#pragma unroll
            for (int j = 0; j < 2; ++j) {
                int np = nbase + j;
                uint32_t Bl[4];
                uint32_t boff =
                    sw128((uint32_t)((np * 16 + rBq) * 128 + (k0 + cBo) * 2));
                LDSM4(Bl, sb + 5 * TILE + boff);
                const uint32_t* Bh = BhR[kst][j];
                float* d0 = d[2 * j];
                float* d1 = d[2 * j + 1];
                MMA(d0, Ah, Bh[0], Bh[2]); MMA(d1, Ah, Bh[1], Bh[3]);
                MMA(d0, Ah, Bl[0], Bl[2]); MMA(d1, Ah, Bl[1], Bl[3]);
                MMA(d0, Al, Bh[0], Bh[2]); MMA(d1, Al, Bh[1], Bh[3]);
            }
        }

        float* Ob = O + (row0 + s * 64) * C;
#pragma unroll
        for (int j = 0; j < 2; ++j) {
            int np = nbase + j;
            *(float2*)(Ob + (size_t)mrow * C + np * 16 + mcol) =
                make_float2(d[2 * j][0], d[2 * j][1]);
            *(float2*)(Ob + (size_t)(mrow + 8) * C + np * 16 + mcol) =
                make_float2(d[2 * j][2], d[2 * j][3]);
            *(float2*)(Ob + (size_t)mrow * C + np * 16 + 8 + mcol) =
                make_float2(d[2 * j + 1][0], d[2 * j + 1][1]);
            *(float2*)(Ob + (size_t)(mrow + 8) * C + np * 16 + 8 + mcol) =
                make_float2(d[2 * j + 1][2], d[2 * j + 1][3]);
        }
        // no trailing barrier: next STS goes to the other V buffer
    }
}

// ---------------------------------------------------------------------------
extern "C" void kernel_launch(void* const* d_in, const int* in_sizes, int n_in,
                              void* d_out, int out_size) {
    const float* q = (const float*)d_in[0];
    const float* k = (const float*)d_in[1];
    const float* v = (const float*)d_in[2];
    float* out = (float*)d_out;

    k1_scores<<<BATCH * CHUNKS, 256>>>(q, k);
    k3_out<<<BATCH * CHUNKS, 256>>>(v, out);
}

// round 14
// speedup vs baseline: 1.2095x; 1.2095x over previous
#include <cuda_runtime.h>
#include <cuda_fp16.h>
#include <cstdint>

#define BATCH 16
#define HW    16384
#define C     64
#define CHUNKS 32            // 512 rows per CTA

__device__ float g_partial[BATCH * CHUNKS * C * C];   // 8 MB scratch
__device__ float g_attn[BATCH * C * C];

// ---------------------------------------------------------------------------
// helpers
// ---------------------------------------------------------------------------
__device__ __forceinline__ uint32_t smem_u32(const void* p) {
    uint32_t a;
    asm("{ .reg .u64 t; cvta.to.shared.u64 t, %1; cvt.u32.u64 %0, t; }"
        : "=r"(a) : "l"(p));
    return a;
}
__device__ __forceinline__ uint32_t sw128(uint32_t o) {
    return o ^ ((o >> 3) & 0x70);
}
__device__ __forceinline__ uint32_t h2u(__half2 h) {
    return *reinterpret_cast<uint32_t*>(&h);
}

#define LDSM4T(r, a)                                                          \
    asm volatile("ldmatrix.sync.aligned.m8n8.x4.trans.shared.b16 "            \
                 "{%0,%1,%2,%3}, [%4];"                                       \
                 : "=r"((r)[0]), "=r"((r)[1]), "=r"((r)[2]), "=r"((r)[3])     \
                 : "r"(a))
#define LDSM4(r, a)                                                           \
    asm volatile("ldmatrix.sync.aligned.m8n8.x4.shared.b16 "                  \
                 "{%0,%1,%2,%3}, [%4];"                                       \
                 : "=r"((r)[0]), "=r"((r)[1]), "=r"((r)[2]), "=r"((r)[3])     \
                 : "r"(a))
#define MMA(d, a, b0, b1)                                                     \
    asm volatile("mma.sync.aligned.m16n8k16.row.col.f32.f16.f16.f32 "         \
                 "{%0,%1,%2,%3}, {%4,%5,%6,%7}, {%8,%9}, {%0,%1,%2,%3};"      \
                 : "+f"((d)[0]), "+f"((d)[1]), "+f"((d)[2]), "+f"((d)[3])     \
                 : "r"((a)[0]), "r"((a)[1]), "r"((a)[2]), "r"((a)[3]),        \
                   "r"(b0), "r"(b1))

// tile: 64 rows x 64 fp16 cols, 128B row stride, SW128 swizzle, 8KB
#define TILE 8192

// exact Dekker split of 4 floats into hi/lo fp16x2 pairs
__device__ __forceinline__ void split4(float4 x, uint32_t& h0, uint32_t& h1,
                                       uint32_t& l0, uint32_t& l1) {
    __half2 a01 = __floats2half2_rn(x.x, x.y);
    __half2 a23 = __floats2half2_rn(x.z, x.w);
    float2 f01 = __half22float2(a01);
    float2 f23 = __half22float2(a23);
    __half2 b01 = __floats2half2_rn(x.x - f01.x, x.y - f01.y);
    __half2 b23 = __floats2half2_rn(x.z - f23.x, x.w - f23.y);
    h0 = h2u(a01); h1 = h2u(a23); l0 = h2u(b01); l1 = h2u(b23);
}
// hi-only pack (for k3 V staging — Vl term dropped by design)
__device__ __forceinline__ void pack4(float4 x, uint32_t& h0, uint32_t& h1) {
    h0 = h2u(__floats2half2_rn(x.x, x.y));
    h1 = h2u(__floats2half2_rn(x.z, x.w));
}

// ---------------------------------------------------------------------------
// Kernel 1 (R12 form, best measured 29.95us): partial scores.
// 8 warps, 32x32 subtiles, 2-way k-split, double-buffered tiles,
// register prefetch; k-halves reduced in smem; one slice per chunk.
// ---------------------------------------------------------------------------
__global__ void __launch_bounds__(256, 2)
k1_scores(const float* __restrict__ Q, const float* __restrict__ K) {
    __shared__ __align__(1024) uint8_t sm[8 * TILE];   // [buf][Qh Ql Kh Kl]
    uint32_t sb = smem_u32(sm);

    int t = threadIdx.x, lane = t & 31, w = t >> 5;
    int b = blockIdx.x >> 5;
    int chunk = blockIdx.x & 31;
    int wk = w >> 2;
    int sub = w & 3;
    int qb32 = (sub >> 1) * 32;
    int nb32 = (sub & 1) * 32;

    const float* Qb = Q + ((size_t)b * HW + chunk * 512) * C;
    const float* Kb = K + ((size_t)b * HW + chunk * 512) * C;

    int rr[4], cc[4];
#pragma unroll
    for (int it = 0; it < 4; ++it) {
        int idx = t + it * 256;
        rr[it] = idx >> 4;
        cc[it] = (idx & 15) * 4;
    }

    float d[2][4][4];
#pragma unroll
    for (int i = 0; i < 2; ++i)
#pragma unroll
        for (int j = 0; j < 4; ++j)
#pragma unroll
            for (int e = 0; e < 4; ++e) d[i][j][e] = 0.f;

    const int li = lane & 7, mi = lane >> 3;
    const int rA = ((mi & 2) << 2) + li;
    const int cA0 = qb32 + ((mi & 1) << 3);
    const int rB = ((mi & 1) << 3) + li;
    const int cBo = (mi & 2) << 2;

    float4 pq[4], pk[4];
#pragma unroll
    for (int it = 0; it < 4; ++it) {
        pq[it] = *(const float4*)(Qb + (size_t)rr[it] * C + cc[it]);
        pk[it] = *(const float4*)(Kb + (size_t)rr[it] * C + cc[it]);
    }

    for (int s = 0; s < 8; ++s) {
        uint32_t base = (uint32_t)((s & 1) * 4 * TILE);
#pragma unroll
        for (int it = 0; it < 4; ++it) {
            uint32_t off = base + sw128((uint32_t)(rr[it] * 128 + cc[it] * 2));
            uint32_t h0, h1, l0, l1;
            split4(pq[it], h0, h1, l0, l1);
            *(uint2*)(sm + 0 * TILE + off) = make_uint2(h0, h1);
            *(uint2*)(sm + 1 * TILE + off) = make_uint2(l0, l1);
            split4(pk[it], h0, h1, l0, l1);
            *(uint2*)(sm + 2 * TILE + off) = make_uint2(h0, h1);
            *(uint2*)(sm + 3 * TILE + off) = make_uint2(l0, l1);
        }
        __syncthreads();

        if (s < 7) {
            const float* Qn = Qb + (size_t)(s + 1) * 64 * C;
            const float* Kn = Kb + (size_t)(s + 1) * 64 * C;
#pragma unroll
            for (int it = 0; it < 4; ++it) {
                pq[it] = *(const float4*)(Qn + (size_t)rr[it] * C + cc[it]);
                pk[it] = *(const float4*)(Kn + (size_t)rr[it] * C + cc[it]);
            }
        }

#pragma unroll
        for (int k2i = 0; k2i < 2; ++k2i) {
            int r0 = (wk * 2 + k2i) * 16;
            uint32_t Ah[2][4], Al[2][4], Bh[2][4], Bl[2][4];
#pragma unroll
            for (int mb = 0; mb < 2; ++mb) {
                uint32_t aoff =
                    base + sw128((uint32_t)((r0 + rA) * 128 + (cA0 + mb * 16) * 2));
                LDSM4T(Ah[mb], sb + 0 * TILE + aoff);
                LDSM4T(Al[mb], sb + 1 * TILE + aoff);
            }
#pragma unroll
            for (int np = 0; np < 2; ++np) {
                uint32_t boff =
                    base + sw128((uint32_t)((r0 + rB) * 128 + (nb32 + np * 16 + cBo) * 2));
                LDSM4T(Bh[np], sb + 2 * TILE + boff);
                LDSM4T(Bl[np], sb + 3 * TILE + boff);
            }
#pragma unroll
            for (int mb = 0; mb < 2; ++mb)
#pragma unroll
                for (int np = 0; np < 2; ++np) {
                    float* d0 = d[mb][np * 2];
                    float* d1 = d[mb][np * 2 + 1];
                    MMA(d0, Ah[mb], Bh[np][0], Bh[np][1]);
                    MMA(d1, Ah[mb], Bh[np][2], Bh[np][3]);
                    MMA(d0, Ah[mb], Bl[np][0], Bl[np][1]);
                    MMA(d1, Ah[mb], Bl[np][2], Bl[np][3]);
                    MMA(d0, Al[mb], Bh[np][0], Bh[np][1]);
                    MMA(d1, Al[mb], Bh[np][2], Bh[np][3]);
                }
        }
    }

    // epilogue: pairwise k-half reduction in smem, one slice per chunk
    __syncthreads();
    float* sred = (float*)sm;
    if (wk == 1) {
#pragma unroll
        for (int mb = 0; mb < 2; ++mb)
#pragma unroll
            for (int j = 0; j < 4; ++j)
#pragma unroll
                for (int e = 0; e < 4; ++e)
                    sred[sub * 1024 + ((mb * 4 + j) * 4 + e) * 32 + lane] =
                        d[mb][j][e];
    }
    __syncthreads();
    if (wk == 0) {
#pragma unroll
        for (int mb = 0; mb < 2; ++mb)
#pragma unroll
            for (int j = 0; j < 4; ++j)
#pragma unroll
                for (int e = 0; e < 4; ++e)
                    d[mb][j][e] +=
                        sred[sub * 1024 + ((mb * 4 + j) * 4 + e) * 32 + lane];

        float* pb = g_partial + ((size_t)b * CHUNKS + chunk) * (C * C);
        int mrow0 = qb32 + (lane >> 2);
        int mcol = 2 * (lane & 3);
#pragma unroll
        for (int mb = 0; mb < 2; ++mb) {
            int r_lo = mrow0 + mb * 16;
#pragma unroll
            for (int np = 0; np < 2; ++np) {
                int c0 = nb32 + np * 16 + mcol;
                *(float2*)(pb + r_lo * C + c0) =
                    make_float2(d[mb][np * 2][0], d[mb][np * 2][1]);
                *(float2*)(pb + (r_lo + 8) * C + c0) =
                    make_float2(d[mb][np * 2][2], d[mb][np * 2][3]);
                *(float2*)(pb + r_lo * C + c0 + 8) =
                    make_float2(d[mb][np * 2 + 1][0], d[mb][np * 2 + 1][1]);
                *(float2*)(pb + (r_lo + 8) * C + c0 + 8) =
                    make_float2(d[mb][np * 2 + 1][2], d[mb][np * 2 + 1][3]);
            }
        }
    }
}

// ---------------------------------------------------------------------------
// Kernel 2: reduce 32 chunk partials + softmax over k.
// ---------------------------------------------------------------------------
__global__ __launch_bounds__(256) void k2_softmax() {
    __shared__ float S[256];
    int b = blockIdx.x >> 4;
    int qg = blockIdx.x & 15;
    int t = threadIdx.x;
    int q = qg * 4 + (t >> 6);
    int k = t & 63;

    const float* p = g_partial + (size_t)b * CHUNKS * (C * C) + q * C + k;
    float acc = 0.f;
#pragma unroll
    for (int ch = 0; ch < CHUNKS; ++ch) acc += p[(size_t)ch * (C * C)];
    S[t] = acc;
    __syncthreads();

    int w = t >> 5, lane = t & 31;
    if (w < 4) {
        float e0 = S[w * 64 + lane];
        float e1 = S[w * 64 + 32 + lane];
        float m = fmaxf(e0, e1);
#pragma unroll
        for (int o = 16; o > 0; o >>= 1) m = fmaxf(m, __shfl_xor_sync(~0u, m, o));
        float x0 = expf(e0 - m), x1 = expf(e1 - m);
        float s = x0 + x1;
#pragma unroll
        for (int o = 16; o > 0; o >>= 1) s += __shfl_xor_sync(~0u, s, o);
        float inv = 1.f / s;
        float* a = g_attn + (size_t)b * (C * C) + (qg * 4 + w) * C;
        a[lane] = x0 * inv;
        a[lane + 32] = x1 * inv;
    }
}

// ---------------------------------------------------------------------------
// Kernel 3 (R9 form, 2-PRODUCT): out[b][r][q] = sum_k attn[b][q][k]*V[b][r][k]
// Computed as Vh*(Ah+Al): V rounded to fp16 (rel err <= 2^-11 of dominant
// term), attn near-exact. Vl tile eliminated: half the V smem traffic,
// 2/3 the MMAs. A = Vh (non-trans, double-buffered), Bh hoisted, Bl smem.
// ---------------------------------------------------------------------------
__global__ void __launch_bounds__(256, 2)
k3_out(const float* __restrict__ V, float* __restrict__ O) {
    __shared__ __align__(1024) uint8_t sm[4 * TILE];   // Vh0 Vh1 Bh Bl
    uint32_t sb = smem_u32(sm);

    int t = threadIdx.x, lane = t & 31, w = t >> 5;
    int b = blockIdx.x >> 5;
    int rg = blockIdx.x & 31;
    size_t row0 = (size_t)b * HW + rg * 512;
    int rowg = (w & 3) * 16;
    int nbase = (w >> 2) * 2;

    int rr[4], cc[4];
#pragma unroll
    for (int it = 0; it < 4; ++it) {
        int idx = t + it * 256;
        rr[it] = idx >> 4;
        cc[it] = (idx & 15) * 4;
    }

    // issue V stage-0 prefetch FIRST (overlaps B staging)
    float4 pv[4];
#pragma unroll
    for (int it = 0; it < 4; ++it)
        pv[it] = *(const float4*)(V + (row0 + rr[it]) * C + cc[it]);

    // stage attn once: B tile [q][k] hi/lo fp16
    const float* ab = g_attn + (size_t)b * (C * C);
#pragma unroll
    for (int it = 0; it < 4; ++it) {
        uint32_t off = sw128((uint32_t)(rr[it] * 128 + cc[it] * 2));
        uint32_t h0, h1, l0, l1;
        split4(*(const float4*)(ab + rr[it] * 64 + cc[it]), h0, h1, l0, l1);
        *(uint2*)(sm + 2 * TILE + off) = make_uint2(h0, h1);
        *(uint2*)(sm + 3 * TILE + off) = make_uint2(l0, l1);
    }
    __syncthreads();   // B tiles visible for the hoisted fragment loads

    const int li = lane & 7, mi = lane >> 3;
    const int rVA = rowg + ((mi & 1) << 3) + li;
    const int cVAo = (mi & 2) << 2;
    const int rBq = ((mi & 1) << 3) + li;
    const int cBo = (mi & 2) << 2;
    int mrow = rowg + (lane >> 2);
    int mcol = 2 * (lane & 3);

    // hoist stage-constant Bh fragments: [kst][np] -> 32 regs
    uint32_t BhR[4][2][4];
#pragma unroll
    for (int kst = 0; kst < 4; ++kst)
#pragma unroll
        for (int j = 0; j < 2; ++j) {
            uint32_t boff = sw128(
                (uint32_t)(((nbase + j) * 16 + rBq) * 128 + (kst * 16 + cBo) * 2));
            LDSM4(BhR[kst][j], sb + 2 * TILE + boff);
        }

    for (int s = 0; s < 8; ++s) {
        uint32_t base = (uint32_t)((s & 1) * TILE);
#pragma unroll
        for (int it = 0; it < 4; ++it) {
            uint32_t off = base + sw128((uint32_t)(rr[it] * 128 + cc[it] * 2));
            uint32_t h0, h1;
            pack4(pv[it], h0, h1);
            *(uint2*)(sm + off) = make_uint2(h0, h1);
        }
        __syncthreads();   // Vh buf ready; buf^1 MMAs transitively done

        if (s < 7) {
            const float* Vn = V + (row0 + (size_t)(s + 1) * 64) * C;
#pragma unroll
            for (int it = 0; it < 4; ++it)
                pv[it] = *(const float4*)(Vn + (size_t)rr[it] * C + cc[it]);
        }

        float d[4][4];
#pragma unroll
        for (int i = 0; i < 4; ++i)
#pragma unroll
            for (int j = 0; j < 4; ++j) d[i][j] = 0.f;

#pragma unroll
        for (int kst = 0; kst < 4; ++kst) {
            int k0 = kst * 16;
            uint32_t Ah[4];
            uint32_t aoff = base + sw128((uint32_t)(rVA * 128 + (k0 + cVAo) * 2));
            LDSM4(Ah, sb + aoff);
#pragma unroll
            for (int j = 0; j < 2; ++j) {
                int np = nbase + j;
                uint32_t Bl[4];
                uint32_t boff =
                    sw128((uint32_t)((np * 16 + rBq) * 128 + (k0 + cBo) * 2));
                LDSM4(Bl, sb + 3 * TILE + boff);
                const uint32_t* Bh = BhR[kst][j];
                float* d0 = d[2 * j];
                float* d1 = d[2 * j + 1];
                MMA(d0, Ah, Bh[0], Bh[2]); MMA(d1, Ah, Bh[1], Bh[3]);
                MMA(d0, Ah, Bl[0], Bl[2]); MMA(d1, Ah, Bl[1], Bl[3]);
            }
        }

        float* Ob = O + (row0 + s * 64) * C;
#pragma unroll
        for (int j = 0; j < 2; ++j) {
            int np = nbase + j;
            *(float2*)(Ob + (size_t)mrow * C + np * 16 + mcol) =
                make_float2(d[2 * j][0], d[2 * j][1]);
            *(float2*)(Ob + (size_t)(mrow + 8) * C + np * 16 + mcol) =
                make_float2(d[2 * j][2], d[2 * j][3]);
            *(float2*)(Ob + (size_t)mrow * C + np * 16 + 8 + mcol) =
                make_float2(d[2 * j + 1][0], d[2 * j + 1][1]);
            *(float2*)(Ob + (size_t)(mrow + 8) * C + np * 16 + 8 + mcol) =
                make_float2(d[2 * j + 1][2], d[2 * j + 1][3]);
        }
        // no trailing barrier: next STS goes to the other Vh buffer
    }
}

// ---------------------------------------------------------------------------
extern "C" void kernel_launch(void* const* d_in, const int* in_sizes, int n_in,
                              void* d_out, int out_size) {
    const float* q = (const float*)d_in[0];
    const float* k = (const float*)d_in[1];
    const float* v = (const float*)d_in[2];
    float* out = (float*)d_out;

    k1_scores<<<BATCH * CHUNKS, 256>>>(q, k);
    k2_softmax<<<BATCH * 16, 256>>>();
    k3_out<<<BATCH * CHUNKS, 256>>>(v, out);
}